// round 2
// baseline (speedup 1.0000x reference)
#include <cuda_runtime.h>
#include <cuda_fp16.h>
#include <cstdint>

#define KK 32768
#define HH 512
#define BM 128
#define BN 128
#define BD 32
#define MT (KK/BM)   // 256 M-tiles

// Static device scratch (no allocations allowed)
__device__ __align__(16) __half g_A[KK*HH];      // c_input in fp16
__device__ __align__(16) __half g_Wt[HH*HH];     // alpha_weight_hh transposed: [n][d]
__device__ float g_awi[HH];                      // input_ @ alpha_weight_ih
__device__ float g_S1p[MT][HH];                  // per-M-tile partial sums
__device__ float g_S2p[MT][HH];
__device__ float g_gates[3*HH];

// ---------------------------------------------------------------- k0: fp32 -> fp16 convert
__global__ void k_convert(const float4* __restrict__ src) {
    int i = blockIdx.x * blockDim.x + threadIdx.x;   // one float4 each
    float4 v = src[i];
    __half2* dst = (__half2*)g_A;
    dst[i*2 + 0] = __floats2half2_rn(v.x, v.y);
    dst[i*2 + 1] = __floats2half2_rn(v.z, v.w);
}

// ---------------------------------------------------------------- k0b: transpose alpha_W_hh -> fp16 [n][d]
__global__ void k_transpose(const float* __restrict__ W) {
    __shared__ float tile[32][33];
    int n0 = blockIdx.x * 32, d0 = blockIdx.y * 32;
    int tx = threadIdx.x, ty = threadIdx.y;          // 32 x 8
    #pragma unroll
    for (int i = 0; i < 32; i += 8)
        tile[ty + i][tx] = W[(d0 + ty + i) * HH + n0 + tx];
    __syncthreads();
    #pragma unroll
    for (int i = 0; i < 32; i += 8)
        g_Wt[(n0 + ty + i) * HH + d0 + tx] = __float2half_rn(tile[tx][ty + i]);
}

// ---------------------------------------------------------------- k0c: alpha_wi = input_ @ alpha_W_ih
__global__ void k_awi(const float* __restrict__ inp, const float* __restrict__ Wa) {
    int h = blockIdx.x * blockDim.x + threadIdx.x;   // [0,512)
    float s = 0.f;
    for (int d = 0; d < HH; d++) s += inp[d] * Wa[d * HH + h];
    g_awi[h] = s;
}

// ---------------------------------------------------------------- k1: fused GEMM + sigmoid/exp + column reduction
__global__ void __launch_bounds__(256, 2) k_main(const float* __restrict__ cinp) {
    const int nt = blockIdx.x;          // 0..3   column block
    const int mt = blockIdx.y;          // 0..255 row block
    const int n0 = nt * BN, k0 = mt * BM;
    const int tid  = threadIdx.x;
    const int lane = tid & 31, wid = tid >> 5;
    const int g = lane >> 2, t = lane & 3;
    const int wm = wid & 3, wn = wid >> 2;       // 4 (M) x 2 (N) warps

    __shared__ __half As[BM * 40];               // stride 40 halves: conflict-free frags, 16B-aligned rows
    __shared__ __half Bs[BN * 40];
    __shared__ float sS1[BN], sS2[BN], sawi[BN];

    if (tid < BN) { sS1[tid] = 0.f; sS2[tid] = 0.f; sawi[tid] = g_awi[n0 + tid]; }

    float acc[2][8][4];
    #pragma unroll
    for (int a = 0; a < 2; a++)
        #pragma unroll
        for (int b = 0; b < 8; b++)
            #pragma unroll
            for (int c = 0; c < 4; c++) acc[a][b][c] = 0.f;

    const uint32_t* As32 = (const uint32_t*)As;
    const uint32_t* Bs32 = (const uint32_t*)Bs;

    for (int d0 = 0; d0 < HH; d0 += BD) {
        __syncthreads();
        // Load A tile [128 x 32] and B tile [128 x 32] halves: 512 uint4 each, 2/thread
        #pragma unroll
        for (int i = 0; i < 2; i++) {
            int idx = tid + i * 256;
            int row = idx >> 2, q = idx & 3;
            uint4 va = *(const uint4*)&g_A[(unsigned)(k0 + row) * HH + d0 + q * 8];
            *(uint4*)&As[row * 40 + q * 8] = va;
            uint4 vb = *(const uint4*)&g_Wt[(unsigned)(n0 + row) * HH + d0 + q * 8];
            *(uint4*)&Bs[row * 40 + q * 8] = vb;
        }
        __syncthreads();
        #pragma unroll
        for (int s = 0; s < 2; s++) {          // two k=16 substeps per BD=32
            uint32_t a[2][4], b[8][2];
            #pragma unroll
            for (int m = 0; m < 2; m++) {
                int r = wm * 32 + m * 16 + g;
                a[m][0] = As32[r * 20 + s * 8 + t];
                a[m][1] = As32[(r + 8) * 20 + s * 8 + t];
                a[m][2] = As32[r * 20 + s * 8 + t + 4];
                a[m][3] = As32[(r + 8) * 20 + s * 8 + t + 4];
            }
            #pragma unroll
            for (int n = 0; n < 8; n++) {
                int c = wn * 64 + n * 8 + g;
                b[n][0] = Bs32[c * 20 + s * 8 + t];
                b[n][1] = Bs32[c * 20 + s * 8 + t + 4];
            }
            #pragma unroll
            for (int m = 0; m < 2; m++)
                #pragma unroll
                for (int n = 0; n < 8; n++)
                    asm volatile(
                        "mma.sync.aligned.m16n8k16.row.col.f32.f16.f16.f32 "
                        "{%0,%1,%2,%3}, {%4,%5,%6,%7}, {%8,%9}, {%0,%1,%2,%3};\n"
                        : "+f"(acc[m][n][0]), "+f"(acc[m][n][1]),
                          "+f"(acc[m][n][2]), "+f"(acc[m][n][3])
                        : "r"(a[m][0]), "r"(a[m][1]), "r"(a[m][2]), "r"(a[m][3]),
                          "r"(b[n][0]), "r"(b[n][1]));
        }
    }
    __syncthreads();

    // Epilogue: e = exp(sigmoid(x + awi[col])); S1 += e; S2 += c_input_f32 * e
    #pragma unroll
    for (int n = 0; n < 8; n++) {
        float s1a = 0.f, s1b = 0.f, s2a = 0.f, s2b = 0.f;
        int colL = wn * 64 + n * 8 + 2 * t;      // local column (pair colL, colL+1)
        float awiA = sawi[colL], awiB = sawi[colL + 1];
        #pragma unroll
        for (int m = 0; m < 2; m++) {
            int rowBase = k0 + wm * 32 + m * 16 + g;
            #pragma unroll
            for (int rr = 0; rr < 2; rr++) {     // rr=0: row g, rr=1: row g+8
                int row = rowBase + rr * 8;
                float xA = acc[m][n][rr * 2 + 0] + awiA;
                float xB = acc[m][n][rr * 2 + 1] + awiB;
                float eA = __expf(__fdividef(1.f, 1.f + __expf(-xA)));
                float eB = __expf(__fdividef(1.f, 1.f + __expf(-xB)));
                s1a += eA; s1b += eB;
                const float* cr = cinp + (unsigned)row * HH + n0 + colL;
                s2a += __ldg(cr)     * eA;
                s2b += __ldg(cr + 1) * eB;
            }
        }
        // reduce over the 8 lanes sharing this column pair (same t, varying g)
        #pragma unroll
        for (int off = 4; off < 32; off <<= 1) {
            s1a += __shfl_xor_sync(0xffffffffu, s1a, off);
            s1b += __shfl_xor_sync(0xffffffffu, s1b, off);
            s2a += __shfl_xor_sync(0xffffffffu, s2a, off);
            s2b += __shfl_xor_sync(0xffffffffu, s2b, off);
        }
        if (g == 0) {
            atomicAdd(&sS1[colL],     s1a);
            atomicAdd(&sS1[colL + 1], s1b);
            atomicAdd(&sS2[colL],     s2a);
            atomicAdd(&sS2[colL + 1], s2b);
        }
    }
    __syncthreads();
    if (tid < BN) {
        g_S1p[mt][n0 + tid] = sS1[tid];
        g_S2p[mt][n0 + tid] = sS2[tid];
    }
}

// ---------------------------------------------------------------- k2: gate pre-activations
__global__ void k_gates(const float* __restrict__ inp, const float* __restrict__ h0,
                        const float* __restrict__ Wih, const float* __restrict__ Whh,
                        const float* __restrict__ bias) {
    int j = blockIdx.x * blockDim.x + threadIdx.x;   // [0, 1536)
    float s = bias[j];
    for (int d = 0; d < HH; d++)
        s += h0[d] * Whh[d * 3 * HH + j] + inp[d] * Wih[d * 3 * HH + j];
    g_gates[j] = s;
}

// ---------------------------------------------------------------- k3: reduce partials + final combine
__global__ void k_final(float* __restrict__ out, int out_size) {
    int h = blockIdx.x * blockDim.x + threadIdx.x;   // [0,512)
    float S1 = 0.f, S2 = 0.f;
    for (int m = 0; m < MT; m++) { S1 += g_S1p[m][h]; S2 += g_S2p[m][h]; }
    float ig = 1.f / (1.f + expf(-g_gates[h]));
    float og = 1.f / (1.f + expf(-g_gates[HH + h]));
    float gg = tanhf(g_gates[2 * HH + h]);
    float E0 = expf(ig);
    float denom = E0 + S1 + 1e-12f;
    float c1 = (gg * E0 + S2) / denom;
    float h1 = og * tanhf(c1);
    out[h] = h1;
    if (out_size >= 2 * HH) out[HH + h] = c1;
}

// ----------------------------------------------------------------
extern "C" void kernel_launch(void* const* d_in, const int* in_sizes, int n_in,
                              void* d_out, int out_size) {
    (void)in_sizes; (void)n_in;
    const float* input_  = (const float*)d_in[0];
    const float* c_input = (const float*)d_in[1];
    const float* h_0     = (const float*)d_in[2];
    /* d_in[3] = c_0, unused by the non-empty-children branch */
    const float* w_ih    = (const float*)d_in[4];
    const float* w_hh    = (const float*)d_in[5];
    const float* bias    = (const float*)d_in[6];
    const float* aw_ih   = (const float*)d_in[7];
    const float* aw_hh   = (const float*)d_in[8];

    k_convert<<<(KK * HH / 4) / 256, 256>>>((const float4*)c_input);
    k_transpose<<<dim3(16, 16), dim3(32, 8)>>>(aw_hh);
    k_awi<<<4, 128>>>(input_, aw_ih);
    k_main<<<dim3(HH / BN, MT), 256>>>(c_input);
    k_gates<<<12, 128>>>(input_, h_0, w_ih, w_hh, bias);
    k_final<<<4, 128>>>((float*)d_out, out_size);
}

// round 3
// speedup vs baseline: 2.2249x; 2.2249x over previous
#include <cuda_runtime.h>
#include <cuda_fp16.h>
#include <cstdint>

#define KK 32768
#define HH 512
#define BM 128
#define BN 128
#define BD 32
#define MT (KK/BM)   // 256 M-tiles

// Static device scratch (no allocations allowed)
__device__ __align__(16) __half g_A[KK*HH];      // c_input in fp16
__device__ __align__(16) __half g_Wt[HH*HH];     // alpha_weight_hh transposed: [n][d]
__device__ float g_awi[HH];                      // input_ @ alpha_weight_ih
__device__ float g_S1p[HH][MT];                  // per-M-tile partial sums, [h][mt] for coalesced reduce
__device__ float g_S2p[HH][MT];
__device__ float g_gates[3*HH];

// -------- PTX helpers --------
__device__ __forceinline__ void ldsm4(uint32_t& r0, uint32_t& r1, uint32_t& r2, uint32_t& r3,
                                      uint32_t saddr) {
    asm volatile("ldmatrix.sync.aligned.m8n8.x4.shared.b16 {%0,%1,%2,%3}, [%4];\n"
                 : "=r"(r0), "=r"(r1), "=r"(r2), "=r"(r3) : "r"(saddr));
}
__device__ __forceinline__ void cp16(uint32_t dst, const void* src) {
    asm volatile("cp.async.ca.shared.global [%0], [%1], 16;\n" :: "r"(dst), "l"(src));
}
#define CP_COMMIT() asm volatile("cp.async.commit_group;\n" ::: "memory")
#define CP_WAIT(n)  asm volatile("cp.async.wait_group %0;\n" :: "n"(n) : "memory")

// ---------------------------------------------------------------- k0: fp32 -> fp16 convert
__global__ void k_convert(const float4* __restrict__ src) {
    int i = blockIdx.x * blockDim.x + threadIdx.x;   // one float4 each
    float4 v = src[i];
    __half2* dst = (__half2*)g_A;
    dst[i*2 + 0] = __floats2half2_rn(v.x, v.y);
    dst[i*2 + 1] = __floats2half2_rn(v.z, v.w);
}

// ---------------------------------------------------------------- k0b: transpose alpha_W_hh -> fp16 [n][d]
__global__ void k_transpose(const float* __restrict__ W) {
    __shared__ float tile[32][33];
    int n0 = blockIdx.x * 32, d0 = blockIdx.y * 32;
    int tx = threadIdx.x, ty = threadIdx.y;          // 32 x 8
    #pragma unroll
    for (int i = 0; i < 32; i += 8)
        tile[ty + i][tx] = W[(d0 + ty + i) * HH + n0 + tx];
    __syncthreads();
    #pragma unroll
    for (int i = 0; i < 32; i += 8)
        g_Wt[(n0 + ty + i) * HH + d0 + tx] = __float2half_rn(tile[tx][ty + i]);
}

// ---------------------------------------------------------------- k_gawi: gates (1536) + awi (512) GEMVs
// block = 256 threads as (ty=tid/16 in [0,16), tx=tid%16); 16 outputs per block, d split 16 ways.
__global__ void k_gawi(const float* __restrict__ inp, const float* __restrict__ h0,
                       const float* __restrict__ Wih, const float* __restrict__ Whh,
                       const float* __restrict__ bias, const float* __restrict__ aWih) {
    __shared__ float sm[16][17];
    int tx = threadIdx.x & 15, ty = threadIdx.x >> 4;
    int b = blockIdx.x;
    float p = 0.f;
    if (b < 96) {                      // gates: j in [0,1536)
        int j = b * 16 + tx;
        for (int d = ty; d < HH; d += 16)
            p += h0[d] * __ldg(&Whh[d * 3 * HH + j]) + inp[d] * __ldg(&Wih[d * 3 * HH + j]);
        sm[ty][tx] = p;
        __syncthreads();
        if (ty == 0) {
            float s = bias[j];
            #pragma unroll
            for (int i = 0; i < 16; i++) s += sm[i][tx];
            g_gates[j] = s;
        }
    } else {                           // awi: jj in [0,512)
        int jj = (b - 96) * 16 + tx;
        for (int d = ty; d < HH; d += 16)
            p += inp[d] * __ldg(&aWih[d * HH + jj]);
        sm[ty][tx] = p;
        __syncthreads();
        if (ty == 0) {
            float s = 0.f;
            #pragma unroll
            for (int i = 0; i < 16; i++) s += sm[i][tx];
            g_awi[jj] = s;
        }
    }
}

// ---------------------------------------------------------------- k1: fused GEMM + sigmoid/exp + column reduction
__global__ void __launch_bounds__(256, 2) k_main() {
    const int nt = blockIdx.x;          // 0..3   column block
    const int mt = blockIdx.y;          // 0..255 row block
    const int n0 = nt * BN, k0 = mt * BM;
    const int tid  = threadIdx.x;
    const int lane = tid & 31, wid = tid >> 5;
    const int g = lane >> 2, t = lane & 3;
    const int wm = wid & 3, wn = wid >> 2;       // 4 (M) x 2 (N) warps

    __shared__ __half As[2][BM * 40];            // stride 40 halves (80B = 5*16B), conflict-free
    __shared__ __half Bs[2][BN * 40];
    __shared__ float sS1[BN], sS2[BN], sawi[BN];

    if (tid < BN) { sS1[tid] = 0.f; sS2[tid] = 0.f; sawi[tid] = g_awi[n0 + tid]; }

    const uint32_t as_base = (uint32_t)__cvta_generic_to_shared(As);
    const uint32_t bs_base = (uint32_t)__cvta_generic_to_shared(Bs);

    float acc[2][8][4];
    #pragma unroll
    for (int a = 0; a < 2; a++)
        #pragma unroll
        for (int b = 0; b < 8; b++)
            #pragma unroll
            for (int c = 0; c < 4; c++) acc[a][b][c] = 0.f;

    const int ldr = tid >> 2, ldq = tid & 3;     // 4 threads per row, rows ldr and ldr+64

    // prefetch tile `it` into buffer `buf`
    #define PREFETCH(it, buf) do {                                                   \
        int d0 = (it) * BD;                                                          \
        _Pragma("unroll")                                                            \
        for (int i = 0; i < 2; i++) {                                                \
            int r = ldr + i * 64;                                                    \
            cp16(as_base + (buf) * (BM*40*2) + (r * 40 + ldq * 8) * 2,               \
                 &g_A[(unsigned)(k0 + r) * HH + d0 + ldq * 8]);                      \
            cp16(bs_base + (buf) * (BN*40*2) + (r * 40 + ldq * 8) * 2,               \
                 &g_Wt[(unsigned)(n0 + r) * HH + d0 + ldq * 8]);                     \
        }                                                                            \
    } while (0)

    PREFETCH(0, 0);
    CP_COMMIT();

    const int rowA = wm * 32 + (lane & 15);
    const int acol = (lane >> 4) << 3;           // 0 or 8
    const int rowB = wn * 64 + (lane & 7) + ((lane >> 4) << 3);
    const int bcol = lane & 8;

    for (int it = 0; it < HH / BD; it++) {
        int buf = it & 1;
        if (it + 1 < HH / BD) {
            PREFETCH(it + 1, buf ^ 1);
            CP_COMMIT();
            CP_WAIT(1);
        } else {
            CP_WAIT(0);
        }
        __syncthreads();

        #pragma unroll
        for (int s = 0; s < 2; s++) {            // two k=16 substeps per BD=32
            int kb = s * 16;
            uint32_t b[8][2];
            #pragma unroll
            for (int np = 0; np < 4; np++) {
                uint32_t baddr = bs_base + buf * (BN*40*2)
                               + (((unsigned)(rowB + np * 16)) * 40 + kb + bcol) * 2;
                ldsm4(b[np*2][0], b[np*2][1], b[np*2+1][0], b[np*2+1][1], baddr);
            }
            uint32_t a[2][4];
            #pragma unroll
            for (int m = 0; m < 2; m++) {
                uint32_t aaddr = as_base + buf * (BM*40*2)
                               + (((unsigned)(rowA + m * 16)) * 40 + kb + acol) * 2;
                ldsm4(a[m][0], a[m][1], a[m][2], a[m][3], aaddr);
            }
            #pragma unroll
            for (int m = 0; m < 2; m++)
                #pragma unroll
                for (int n = 0; n < 8; n++)
                    asm volatile(
                        "mma.sync.aligned.m16n8k16.row.col.f32.f16.f16.f32 "
                        "{%0,%1,%2,%3}, {%4,%5,%6,%7}, {%8,%9}, {%0,%1,%2,%3};\n"
                        : "+f"(acc[m][n][0]), "+f"(acc[m][n][1]),
                          "+f"(acc[m][n][2]), "+f"(acc[m][n][3])
                        : "r"(a[m][0]), "r"(a[m][1]), "r"(a[m][2]), "r"(a[m][3]),
                          "r"(b[n][0]), "r"(b[n][1]));
        }
        __syncthreads();
    }

    // Epilogue: e = exp(sigmoid(x + awi[col])); S1 += e; S2 += c_input(fp16) * e
    #pragma unroll
    for (int n = 0; n < 8; n++) {
        float s1a = 0.f, s1b = 0.f, s2a = 0.f, s2b = 0.f;
        int colL = wn * 64 + n * 8 + 2 * t;      // local column (pair colL, colL+1)
        float awiA = sawi[colL], awiB = sawi[colL + 1];
        #pragma unroll
        for (int m = 0; m < 2; m++) {
            int rowBase = k0 + wm * 32 + m * 16 + g;
            #pragma unroll
            for (int rr = 0; rr < 2; rr++) {     // rr=0: row g, rr=1: row g+8
                int row = rowBase + rr * 8;
                float xA = acc[m][n][rr * 2 + 0] + awiA;
                float xB = acc[m][n][rr * 2 + 1] + awiB;
                float eA = __expf(__fdividef(1.f, 1.f + __expf(-xA)));
                float eB = __expf(__fdividef(1.f, 1.f + __expf(-xB)));
                s1a += eA; s1b += eB;
                float2 cf = __half22float2(
                    *(const __half2*)&g_A[(unsigned)row * HH + n0 + colL]);
                s2a += cf.x * eA;
                s2b += cf.y * eB;
            }
        }
        // reduce over the 8 lanes sharing this column pair (same t, varying g)
        #pragma unroll
        for (int off = 4; off < 32; off <<= 1) {
            s1a += __shfl_xor_sync(0xffffffffu, s1a, off);
            s1b += __shfl_xor_sync(0xffffffffu, s1b, off);
            s2a += __shfl_xor_sync(0xffffffffu, s2a, off);
            s2b += __shfl_xor_sync(0xffffffffu, s2b, off);
        }
        if (g == 0) {
            atomicAdd(&sS1[colL],     s1a);
            atomicAdd(&sS1[colL + 1], s1b);
            atomicAdd(&sS2[colL],     s2a);
            atomicAdd(&sS2[colL + 1], s2b);
        }
    }
    __syncthreads();
    if (tid < BN) {
        g_S1p[n0 + tid][mt] = sS1[tid];
        g_S2p[n0 + tid][mt] = sS2[tid];
    }
}

// ---------------------------------------------------------------- k3: reduce partials + final combine
// 64 blocks x 256 threads; one warp per h (512 warps), coalesced over mt.
__global__ void k_final(float* __restrict__ out, int out_size) {
    int w = (blockIdx.x * blockDim.x + threadIdx.x) >> 5;  // [0,512)
    int lane = threadIdx.x & 31;
    float S1 = 0.f, S2 = 0.f;
    #pragma unroll
    for (int m = lane; m < MT; m += 32) {
        S1 += g_S1p[w][m];
        S2 += g_S2p[w][m];
    }
    #pragma unroll
    for (int off = 16; off > 0; off >>= 1) {
        S1 += __shfl_xor_sync(0xffffffffu, S1, off);
        S2 += __shfl_xor_sync(0xffffffffu, S2, off);
    }
    if (lane == 0) {
        int h = w;
        float ig = 1.f / (1.f + expf(-g_gates[h]));
        float og = 1.f / (1.f + expf(-g_gates[HH + h]));
        float gg = tanhf(g_gates[2 * HH + h]);
        float E0 = expf(ig);
        float denom = E0 + S1 + 1e-12f;
        float c1 = (gg * E0 + S2) / denom;
        float h1 = og * tanhf(c1);
        out[h] = h1;
        if (out_size >= 2 * HH) out[HH + h] = c1;
    }
}

// ----------------------------------------------------------------
extern "C" void kernel_launch(void* const* d_in, const int* in_sizes, int n_in,
                              void* d_out, int out_size) {
    (void)in_sizes; (void)n_in;
    const float* input_  = (const float*)d_in[0];
    const float* c_input = (const float*)d_in[1];
    const float* h_0     = (const float*)d_in[2];
    /* d_in[3] = c_0, unused by the non-empty-children branch */
    const float* w_ih    = (const float*)d_in[4];
    const float* w_hh    = (const float*)d_in[5];
    const float* bias    = (const float*)d_in[6];
    const float* aw_ih   = (const float*)d_in[7];
    const float* aw_hh   = (const float*)d_in[8];

    k_convert<<<(KK * HH / 4) / 256, 256>>>((const float4*)c_input);
    k_transpose<<<dim3(16, 16), dim3(32, 8)>>>(aw_hh);
    k_gawi<<<128, 256>>>(input_, h_0, w_ih, w_hh, bias, aw_ih);
    k_main<<<dim3(HH / BN, MT), 256>>>();
    k_final<<<64, 256>>>((float*)d_out, out_size);
}

// round 5
// speedup vs baseline: 2.3614x; 1.0614x over previous
#include <cuda_runtime.h>
#include <cuda_fp16.h>
#include <cstdint>

#define KK 32768
#define HH 512
#define BM 128
#define BN 256
#define BD 64
#define KT (HH/BD)   // 8 k-tiles
#define MT (KK/BM)   // 256 M-tiles
#define NSTAGE 3

// Static device scratch (no allocations allowed)
__device__ __align__(16) __half g_A[KK*HH];      // c_input in fp16
__device__ __align__(16) __half g_Wt[HH*HH];     // alpha_weight_hh transposed: [n][d]
__device__ float g_awi[HH];                      // input_ @ alpha_weight_ih
__device__ float g_S1p[HH][MT];                  // per-M-tile partials, [h][mt]
__device__ float g_S2p[HH][MT];
__device__ float g_gates[3*HH];

// -------- PTX helpers --------
__device__ __forceinline__ void ldsm4(uint32_t& r0, uint32_t& r1, uint32_t& r2, uint32_t& r3,
                                      uint32_t saddr) {
    asm volatile("ldmatrix.sync.aligned.m8n8.x4.shared.b16 {%0,%1,%2,%3}, [%4];\n"
                 : "=r"(r0), "=r"(r1), "=r"(r2), "=r"(r3) : "r"(saddr));
}
__device__ __forceinline__ void cp16(uint32_t dst, const void* src) {
    asm volatile("cp.async.cg.shared.global [%0], [%1], 16;\n" :: "r"(dst), "l"(src));
}
#define CP_COMMIT() asm volatile("cp.async.commit_group;\n" ::: "memory")
#define CP_WAIT(n)  asm volatile("cp.async.wait_group %0;\n" :: "n"(n) : "memory")
#define SWZ(off) ((off) ^ (((off) >> 3) & 0x70))

// SMEM layout (dynamic)
#define OFF_SAWI 0
#define OFF_S1   1024
#define OFF_S2   2048
#define OFF_T0   4096
#define ASZ      (BM*BD*2)          // 16384
#define BSZ      (BN*BD*2)          // 32768
#define STG      (ASZ+BSZ)          // 49152
#define SMEM_TOTAL (OFF_T0 + NSTAGE*STG)   // 151552

// ---------------------------------------------------------------- k_prep: convert + transpose + gemvs in one launch
__global__ void k_prep(const float4* __restrict__ csrc,
                       const float* __restrict__ Walpha,
                       const float* __restrict__ inp, const float* __restrict__ h0,
                       const float* __restrict__ Wih, const float* __restrict__ Whh,
                       const float* __restrict__ bias, const float* __restrict__ aWih) {
    int b = blockIdx.x;
    if (b < 4096) {                 // ---- fp32 -> fp16 convert: 4 float4 per thread
        int base = b * 1024 + threadIdx.x;
        __half2* dst = (__half2*)g_A;
        #pragma unroll
        for (int i = 0; i < 4; i++) {
            int idx = base + i * 256;
            float4 v = csrc[idx];
            dst[idx*2 + 0] = __floats2half2_rn(v.x, v.y);
            dst[idx*2 + 1] = __floats2half2_rn(v.z, v.w);
        }
    } else if (b < 4096 + 256) {    // ---- transpose alpha_W_hh -> fp16 [n][d]
        __shared__ float tile[32][33];
        int bb = b - 4096;
        int n0 = (bb & 15) * 32, d0 = (bb >> 4) * 32;
        int tx = threadIdx.x & 31, ty = threadIdx.x >> 5;   // 32 x 8
        #pragma unroll
        for (int i = 0; i < 32; i += 8)
            tile[ty + i][tx] = Walpha[(d0 + ty + i) * HH + n0 + tx];
        __syncthreads();
        #pragma unroll
        for (int i = 0; i < 32; i += 8)
            g_Wt[(n0 + ty + i) * HH + d0 + tx] = __float2half_rn(tile[tx][ty + i]);
    } else {                        // ---- gates (1536) + awi (512) GEMVs
        __shared__ float sm[16][17];
        int bb = b - 4096 - 256;
        int tx = threadIdx.x & 15, ty = threadIdx.x >> 4;
        float p = 0.f;
        if (bb < 96) {
            int j = bb * 16 + tx;
            for (int d = ty; d < HH; d += 16)
                p += h0[d] * __ldg(&Whh[d * 3 * HH + j]) + inp[d] * __ldg(&Wih[d * 3 * HH + j]);
            sm[ty][tx] = p;
            __syncthreads();
            if (ty == 0) {
                float s = bias[j];
                #pragma unroll
                for (int i = 0; i < 16; i++) s += sm[i][tx];
                g_gates[j] = s;
            }
        } else {
            int jj = (bb - 96) * 16 + tx;
            for (int d = ty; d < HH; d += 16)
                p += inp[d] * __ldg(&aWih[d * HH + jj]);
            sm[ty][tx] = p;
            __syncthreads();
            if (ty == 0) {
                float s = 0.f;
                #pragma unroll
                for (int i = 0; i < 16; i++) s += sm[i][tx];
                g_awi[jj] = s;
            }
        }
    }
}

// ---------------------------------------------------------------- k_main: fused GEMM (64x64 warp tiles) + exp(sigmoid) + reduce
__global__ void __launch_bounds__(256, 1) k_main(const float* __restrict__ cinp) {
    extern __shared__ char smem[];
    const uint32_t sb = (uint32_t)__cvta_generic_to_shared(smem);
    const int nt = blockIdx.x;          // 0..1
    const int mt = blockIdx.y;          // 0..255
    const int n0 = nt * BN, k0 = mt * BM;
    const int tid  = threadIdx.x;
    const int lane = tid & 31, w = tid >> 5;
    const int g = lane >> 2, t = lane & 3;
    const int wm = w >> 2, wn = w & 3;   // 2 (M) x 4 (N) warps, 64x64 tiles

    float* sawi = (float*)(smem + OFF_SAWI);
    float* sS1  = (float*)(smem + OFF_S1);
    float* sS2  = (float*)(smem + OFF_S2);
    sawi[tid] = g_awi[n0 + tid];
    sS1[tid] = 0.f; sS2[tid] = 0.f;

    float acc[4][8][4];
    #pragma unroll
    for (int a = 0; a < 4; a++)
        #pragma unroll
        for (int bq = 0; bq < 8; bq++)
            #pragma unroll
            for (int c = 0; c < 4; c++) acc[a][bq][c] = 0.f;

    // tile loader: A 128x64, B 256x64 halves, SW128-swizzled 128B rows
    #define LOADTILE(tt, st) do {                                                   \
        uint32_t abase = sb + OFF_T0 + (st) * STG;                                  \
        uint32_t bbase = abase + ASZ;                                               \
        _Pragma("unroll")                                                           \
        for (int i = 0; i < 4; i++) {                                               \
            int s = tid + i * 256; int r = s >> 3, sc = s & 7;                      \
            uint32_t off = (uint32_t)(r * 128 + sc * 16);                           \
            cp16(abase + SWZ(off), &g_A[(unsigned)(k0 + r) * HH + (tt) * BD + sc * 8]); \
        }                                                                           \
        _Pragma("unroll")                                                           \
        for (int i = 0; i < 8; i++) {                                               \
            int s = tid + i * 256; int r = s >> 3, sc = s & 7;                      \
            uint32_t off = (uint32_t)(r * 128 + sc * 16);                           \
            cp16(bbase + SWZ(off), &g_Wt[(unsigned)(n0 + r) * HH + (tt) * BD + sc * 8]); \
        }                                                                           \
    } while (0)

    LOADTILE(0, 0); CP_COMMIT();
    LOADTILE(1, 1); CP_COMMIT();
    LOADTILE(2, 2); CP_COMMIT();

    const int arow = (lane & 15), asel = (lane >> 4) << 3;       // A frag addressing
    const int brow = (lane & 7) + ((lane >> 4) << 3), bsel = lane & 8;

    for (int tt = 0; tt < KT; tt++) {
        CP_WAIT(2);
        __syncthreads();
        uint32_t abase = sb + OFF_T0 + (tt % NSTAGE) * STG;
        uint32_t bbase = abase + ASZ;
        #pragma unroll
        for (int s = 0; s < 4; s++) {        // four k=16 substeps per BD=64
            int kb = s * 16;
            uint32_t a[4][4], b[8][2];
            #pragma unroll
            for (int mi = 0; mi < 4; mi++) {
                uint32_t off = (uint32_t)((wm * 64 + mi * 16 + arow) * 128 + (kb + asel) * 2);
                ldsm4(a[mi][0], a[mi][1], a[mi][2], a[mi][3], abase + SWZ(off));
            }
            #pragma unroll
            for (int np = 0; np < 4; np++) {
                uint32_t off = (uint32_t)((wn * 64 + np * 16 + brow) * 128 + (kb + bsel) * 2);
                ldsm4(b[np*2][0], b[np*2][1], b[np*2+1][0], b[np*2+1][1], bbase + SWZ(off));
            }
            #pragma unroll
            for (int mi = 0; mi < 4; mi++)
                #pragma unroll
                for (int n = 0; n < 8; n++)
                    asm volatile(
                        "mma.sync.aligned.m16n8k16.row.col.f32.f16.f16.f32 "
                        "{%0,%1,%2,%3}, {%4,%5,%6,%7}, {%8,%9}, {%0,%1,%2,%3};\n"
                        : "+f"(acc[mi][n][0]), "+f"(acc[mi][n][1]),
                          "+f"(acc[mi][n][2]), "+f"(acc[mi][n][3])
                        : "r"(a[mi][0]), "r"(a[mi][1]), "r"(a[mi][2]), "r"(a[mi][3]),
                          "r"(b[n][0]), "r"(b[n][1]));
        }
        __syncthreads();
        if (tt + NSTAGE < KT) LOADTILE(tt + NSTAGE, tt % NSTAGE);
        CP_COMMIT();
    }

    // Epilogue: e = exp(sigmoid(x + awi[col])); S1 += e; S2 += c_input(fp32) * e
    #pragma unroll
    for (int n = 0; n < 8; n++) {
        float s1a = 0.f, s1b = 0.f, s2a = 0.f, s2b = 0.f;
        int colL = wn * 64 + n * 8 + 2 * t;           // local col pair (colL, colL+1)
        float awiA = sawi[colL], awiB = sawi[colL + 1];
        #pragma unroll
        for (int mi = 0; mi < 4; mi++) {
            int rowBase = k0 + wm * 64 + mi * 16 + g;
            #pragma unroll
            for (int rr = 0; rr < 2; rr++) {
                int row = rowBase + rr * 8;
                float xA = acc[mi][n][rr * 2 + 0] + awiA;
                float xB = acc[mi][n][rr * 2 + 1] + awiB;
                float eA = __expf(__fdividef(1.f, 1.f + __expf(-xA)));
                float eB = __expf(__fdividef(1.f, 1.f + __expf(-xB)));
                s1a += eA; s1b += eB;
                float2 cf = *(const float2*)&cinp[(unsigned)row * HH + n0 + colL];
                s2a += cf.x * eA;
                s2b += cf.y * eB;
            }
        }
        #pragma unroll
        for (int off = 4; off < 32; off <<= 1) {
            s1a += __shfl_xor_sync(0xffffffffu, s1a, off);
            s1b += __shfl_xor_sync(0xffffffffu, s1b, off);
            s2a += __shfl_xor_sync(0xffffffffu, s2a, off);
            s2b += __shfl_xor_sync(0xffffffffu, s2b, off);
        }
        if (g == 0) {
            atomicAdd(&sS1[colL],     s1a);
            atomicAdd(&sS1[colL + 1], s1b);
            atomicAdd(&sS2[colL],     s2a);
            atomicAdd(&sS2[colL + 1], s2b);
        }
    }
    __syncthreads();
    g_S1p[n0 + tid][mt] = sS1[tid];
    g_S2p[n0 + tid][mt] = sS2[tid];
}

// ---------------------------------------------------------------- k_final: reduce partials + combine
__global__ void k_final(float* __restrict__ out, int out_size) {
    int wg = (blockIdx.x * blockDim.x + threadIdx.x) >> 5;  // [0,512)
    int lane = threadIdx.x & 31;
    float S1 = 0.f, S2 = 0.f;
    #pragma unroll
    for (int m = lane; m < MT; m += 32) {
        S1 += g_S1p[wg][m];
        S2 += g_S2p[wg][m];
    }
    #pragma unroll
    for (int off = 16; off > 0; off >>= 1) {
        S1 += __shfl_xor_sync(0xffffffffu, S1, off);
        S2 += __shfl_xor_sync(0xffffffffu, S2, off);
    }
    if (lane == 0) {
        int h = wg;
        float ig = 1.f / (1.f + expf(-g_gates[h]));
        float og = 1.f / (1.f + expf(-g_gates[HH + h]));
        float gg = tanhf(g_gates[2 * HH + h]);
        float E0 = expf(ig);
        float denom = E0 + S1 + 1e-12f;
        float c1 = (gg * E0 + S2) / denom;
        float h1 = og * tanhf(c1);
        out[h] = h1;
        if (out_size >= 2 * HH) out[HH + h] = c1;
    }
}

// ----------------------------------------------------------------
extern "C" void kernel_launch(void* const* d_in, const int* in_sizes, int n_in,
                              void* d_out, int out_size) {
    (void)in_sizes; (void)n_in;
    const float* input_  = (const float*)d_in[0];
    const float* c_input = (const float*)d_in[1];
    const float* h_0     = (const float*)d_in[2];
    /* d_in[3] = c_0, unused by the non-empty-children branch */
    const float* w_ih    = (const float*)d_in[4];
    const float* w_hh    = (const float*)d_in[5];
    const float* bias    = (const float*)d_in[6];
    const float* aw_ih   = (const float*)d_in[7];
    const float* aw_hh   = (const float*)d_in[8];

    static int smem_set = 0;
    if (!smem_set) {
        cudaFuncSetAttribute(k_main, cudaFuncAttributeMaxDynamicSharedMemorySize, SMEM_TOTAL);
        smem_set = 1;
    }

    k_prep<<<4096 + 256 + 128, 256>>>((const float4*)c_input, aw_hh,
                                      input_, h_0, w_ih, w_hh, bias, aw_ih);
    k_main<<<dim3(HH / BN, MT), 256, SMEM_TOTAL>>>(c_input);
    k_final<<<64, 256>>>((float*)d_out, out_size);
}

// round 6
// speedup vs baseline: 2.8022x; 1.1867x over previous
#include <cuda_runtime.h>
#include <cuda_fp16.h>
#include <cstdint>

#define KK 32768
#define HH 512
#define BM 128
#define BN 256
#define BD 64
#define KT (HH/BD)   // 8 k-tiles
#define MT (KK/BM)   // 256 M-tiles
#define NSTAGE 3

// Static device scratch (no allocations allowed)
__device__ __align__(16) __half g_Wt[HH*HH];     // alpha_weight_hh transposed: [n][d]
__device__ float g_awi[HH];                      // input_ @ alpha_weight_ih
__device__ float g_S1p[HH][MT];                  // per-M-tile partials, [h][mt]
__device__ float g_S2p[HH][MT];
__device__ float g_gates[3*HH];

// -------- PTX helpers --------
__device__ __forceinline__ void ldsm4(uint32_t& r0, uint32_t& r1, uint32_t& r2, uint32_t& r3,
                                      uint32_t saddr) {
    asm volatile("ldmatrix.sync.aligned.m8n8.x4.shared.b16 {%0,%1,%2,%3}, [%4];\n"
                 : "=r"(r0), "=r"(r1), "=r"(r2), "=r"(r3) : "r"(saddr));
}
__device__ __forceinline__ void cp16(uint32_t dst, const void* src) {
    asm volatile("cp.async.cg.shared.global [%0], [%1], 16;\n" :: "r"(dst), "l"(src));
}
#define CP_COMMIT() asm volatile("cp.async.commit_group;\n" ::: "memory")
#define CP_WAIT(n)  asm volatile("cp.async.wait_group %0;\n" :: "n"(n) : "memory")
#define SWZ(off) ((off) ^ (((off) >> 3) & 0x70))

__device__ __forceinline__ void sts128(uint32_t addr, uint32_t x, uint32_t y,
                                       uint32_t z, uint32_t w) {
    asm volatile("st.shared.v4.b32 [%0], {%1,%2,%3,%4};\n"
                 :: "r"(addr), "r"(x), "r"(y), "r"(z), "r"(w) : "memory");
}
__device__ __forceinline__ uint32_t h2u(__half2 h) { return *(uint32_t*)&h; }

// SMEM layout (dynamic)
#define OFF_SAWI 0
#define OFF_S1   1024
#define OFF_S2   2048
#define OFF_T0   4096
#define ASZ      (BM*BD*2)          // 16384
#define BSZ      (BN*BD*2)          // 32768
#define STG      (ASZ+BSZ)          // 49152
#define SMEM_TOTAL (OFF_T0 + NSTAGE*STG)   // 151552

// ---------------------------------------------------------------- k_prep: transpose + gemvs
__global__ void k_prep(const float* __restrict__ Walpha,
                       const float* __restrict__ inp, const float* __restrict__ h0,
                       const float* __restrict__ Wih, const float* __restrict__ Whh,
                       const float* __restrict__ bias, const float* __restrict__ aWih) {
    int b = blockIdx.x;
    if (b < 256) {                  // ---- transpose alpha_W_hh -> fp16 [n][d]
        __shared__ float tile[32][33];
        int n0 = (b & 15) * 32, d0 = (b >> 4) * 32;
        int tx = threadIdx.x & 31, ty = threadIdx.x >> 5;   // 32 x 8
        #pragma unroll
        for (int i = 0; i < 32; i += 8)
            tile[ty + i][tx] = Walpha[(d0 + ty + i) * HH + n0 + tx];
        __syncthreads();
        #pragma unroll
        for (int i = 0; i < 32; i += 8)
            g_Wt[(n0 + ty + i) * HH + d0 + tx] = __float2half_rn(tile[tx][ty + i]);
    } else {                        // ---- gates (1536) + awi (512) GEMVs
        __shared__ float sm[16][17];
        int bb = b - 256;
        int tx = threadIdx.x & 15, ty = threadIdx.x >> 4;
        float p = 0.f;
        if (bb < 96) {
            int j = bb * 16 + tx;
            for (int d = ty; d < HH; d += 16)
                p += h0[d] * __ldg(&Whh[d * 3 * HH + j]) + inp[d] * __ldg(&Wih[d * 3 * HH + j]);
            sm[ty][tx] = p;
            __syncthreads();
            if (ty == 0) {
                float s = bias[j];
                #pragma unroll
                for (int i = 0; i < 16; i++) s += sm[i][tx];
                g_gates[j] = s;
            }
        } else {
            int jj = (bb - 96) * 16 + tx;
            for (int d = ty; d < HH; d += 16)
                p += inp[d] * __ldg(&aWih[d * HH + jj]);
            sm[ty][tx] = p;
            __syncthreads();
            if (ty == 0) {
                float s = 0.f;
                #pragma unroll
                for (int i = 0; i < 16; i++) s += sm[i][tx];
                g_awi[jj] = s;
            }
        }
    }
}

// ---------------------------------------------------------------- k_main: fused convert + GEMM + exp(sigmoid) + reduce
__global__ void __launch_bounds__(256, 1) k_main(const float* __restrict__ cinp) {
    extern __shared__ char smem[];
    const uint32_t sb = (uint32_t)__cvta_generic_to_shared(smem);
    const int nt = blockIdx.x;          // 0..1
    const int mt = blockIdx.y;          // 0..255
    const int n0 = nt * BN, k0 = mt * BM;
    const int tid  = threadIdx.x;
    const int lane = tid & 31, w = tid >> 5;
    const int g = lane >> 2, t = lane & 3;
    const int wm = w >> 2, wn = w & 3;   // 2 (M) x 4 (N) warps, 64x64 tiles

    float* sawi = (float*)(smem + OFF_SAWI);
    float* sS1  = (float*)(smem + OFF_S1);
    float* sS2  = (float*)(smem + OFF_S2);
    sawi[tid] = g_awi[n0 + tid];
    sS1[tid] = 0.f; sS2[tid] = 0.f;

    float acc[4][8][4];
    #pragma unroll
    for (int a = 0; a < 4; a++)
        #pragma unroll
        for (int bq = 0; bq < 8; bq++)
            #pragma unroll
            for (int c = 0; c < 4; c++) acc[a][bq][c] = 0.f;

    // A staging registers: tile held one iteration ahead (fp32, 8 float4/thread)
    float4 areg[4][2];
    const int ar = tid >> 3, ahg = tid & 7;   // thread handles rows ar + i*32, half-group ahg

    // load fp32 A tile tt into registers
    #define LOADA_G(tt) do {                                                        \
        _Pragma("unroll")                                                           \
        for (int i = 0; i < 4; i++) {                                               \
            const float4* p = (const float4*)&cinp[(unsigned)(k0 + ar + i * 32) * HH \
                                                   + (tt) * BD + ahg * 8];          \
            areg[i][0] = __ldg(p); areg[i][1] = __ldg(p + 1);                       \
        }                                                                           \
    } while (0)

    // convert + STS A registers into stage st
    #define STOREA(st) do {                                                         \
        uint32_t abase = sb + OFF_T0 + (st) * STG;                                  \
        _Pragma("unroll")                                                           \
        for (int i = 0; i < 4; i++) {                                               \
            uint32_t off = (uint32_t)((ar + i * 32) * 128 + ahg * 16);              \
            __half2 h0 = __floats2half2_rn(areg[i][0].x, areg[i][0].y);             \
            __half2 h1 = __floats2half2_rn(areg[i][0].z, areg[i][0].w);             \
            __half2 h2 = __floats2half2_rn(areg[i][1].x, areg[i][1].y);             \
            __half2 h3 = __floats2half2_rn(areg[i][1].z, areg[i][1].w);             \
            sts128(abase + SWZ(off), h2u(h0), h2u(h1), h2u(h2), h2u(h3));           \
        }                                                                           \
    } while (0)

    // B tile loader via cp.async (fp16 weights, L2-hot)
    #define LOADB(tt, st) do {                                                      \
        uint32_t bbase = sb + OFF_T0 + (st) * STG + ASZ;                            \
        _Pragma("unroll")                                                           \
        for (int i = 0; i < 8; i++) {                                               \
            int s = tid + i * 256; int r = s >> 3, sc = s & 7;                      \
            uint32_t off = (uint32_t)(r * 128 + sc * 16);                           \
            cp16(bbase + SWZ(off), &g_Wt[(unsigned)(n0 + r) * HH + (tt) * BD + sc * 8]); \
        }                                                                           \
    } while (0)

    // prologue
    LOADA_G(0); STOREA(0);
    LOADA_G(1); STOREA(1);
    LOADA_G(2);                 // held in regs, stored during tt=0
    LOADB(0, 0); CP_COMMIT();
    LOADB(1, 1); CP_COMMIT();
    LOADB(2, 2); CP_COMMIT();

    const int arow = (lane & 15), asel = (lane >> 4) << 3;       // A frag addressing
    const int brow = (lane & 7) + ((lane >> 4) << 3), bsel = lane & 8;

    for (int tt = 0; tt < KT; tt++) {
        CP_WAIT(2);
        __syncthreads();
        uint32_t abase = sb + OFF_T0 + (tt % NSTAGE) * STG;
        uint32_t bbase = abase + ASZ;
        #pragma unroll
        for (int s = 0; s < 4; s++) {        // four k=16 substeps per BD=64
            int kb = s * 16;
            uint32_t a[4][4], b[8][2];
            #pragma unroll
            for (int mi = 0; mi < 4; mi++) {
                uint32_t off = (uint32_t)((wm * 64 + mi * 16 + arow) * 128 + (kb + asel) * 2);
                ldsm4(a[mi][0], a[mi][1], a[mi][2], a[mi][3], abase + SWZ(off));
            }
            #pragma unroll
            for (int np = 0; np < 4; np++) {
                uint32_t off = (uint32_t)((wn * 64 + np * 16 + brow) * 128 + (kb + bsel) * 2);
                ldsm4(b[np*2][0], b[np*2][1], b[np*2+1][0], b[np*2+1][1], bbase + SWZ(off));
            }
            #pragma unroll
            for (int mi = 0; mi < 4; mi++)
                #pragma unroll
                for (int n = 0; n < 8; n++)
                    asm volatile(
                        "mma.sync.aligned.m16n8k16.row.col.f32.f16.f16.f32 "
                        "{%0,%1,%2,%3}, {%4,%5,%6,%7}, {%8,%9}, {%0,%1,%2,%3};\n"
                        : "+f"(acc[mi][n][0]), "+f"(acc[mi][n][1]),
                          "+f"(acc[mi][n][2]), "+f"(acc[mi][n][3])
                        : "r"(a[mi][0]), "r"(a[mi][1]), "r"(a[mi][2]), "r"(a[mi][3]),
                          "r"(b[n][0]), "r"(b[n][1]));
        }
        __syncthreads();
        // A: store tile tt+2 (held in regs) into stage (tt+2)%3, then refill regs with tt+3
        if (tt + 2 < KT) STOREA((tt + 2) % NSTAGE);
        if (tt + 3 < KT) {
            LOADA_G(tt + 3);
            LOADB(tt + 3, (tt + 3) % NSTAGE);
        }
        CP_COMMIT();
    }

    // Epilogue: e = exp(sigmoid(x + awi[col])); S1 += e; S2 += c_input(fp32) * e
    #pragma unroll
    for (int n = 0; n < 8; n++) {
        float s1a = 0.f, s1b = 0.f, s2a = 0.f, s2b = 0.f;
        int colL = wn * 64 + n * 8 + 2 * t;           // local col pair (colL, colL+1)
        float awiA = sawi[colL], awiB = sawi[colL + 1];
        #pragma unroll
        for (int mi = 0; mi < 4; mi++) {
            int rowBase = k0 + wm * 64 + mi * 16 + g;
            #pragma unroll
            for (int rr = 0; rr < 2; rr++) {
                int row = rowBase + rr * 8;
                float xA = acc[mi][n][rr * 2 + 0] + awiA;
                float xB = acc[mi][n][rr * 2 + 1] + awiB;
                float eA = __expf(__fdividef(1.f, 1.f + __expf(-xA)));
                float eB = __expf(__fdividef(1.f, 1.f + __expf(-xB)));
                s1a += eA; s1b += eB;
                float2 cf = *(const float2*)&cinp[(unsigned)row * HH + n0 + colL];
                s2a += cf.x * eA;
                s2b += cf.y * eB;
            }
        }
        #pragma unroll
        for (int off = 4; off < 32; off <<= 1) {
            s1a += __shfl_xor_sync(0xffffffffu, s1a, off);
            s1b += __shfl_xor_sync(0xffffffffu, s1b, off);
            s2a += __shfl_xor_sync(0xffffffffu, s2a, off);
            s2b += __shfl_xor_sync(0xffffffffu, s2b, off);
        }
        if (g == 0) {
            atomicAdd(&sS1[colL],     s1a);
            atomicAdd(&sS1[colL + 1], s1b);
            atomicAdd(&sS2[colL],     s2a);
            atomicAdd(&sS2[colL + 1], s2b);
        }
    }
    __syncthreads();
    g_S1p[n0 + tid][mt] = sS1[tid];
    g_S2p[n0 + tid][mt] = sS2[tid];
}

// ---------------------------------------------------------------- k_final: reduce partials + combine
__global__ void k_final(float* __restrict__ out, int out_size) {
    int wg = (blockIdx.x * blockDim.x + threadIdx.x) >> 5;  // [0,512)
    int lane = threadIdx.x & 31;
    float S1 = 0.f, S2 = 0.f;
    #pragma unroll
    for (int m = lane; m < MT; m += 32) {
        S1 += g_S1p[wg][m];
        S2 += g_S2p[wg][m];
    }
    #pragma unroll
    for (int off = 16; off > 0; off >>= 1) {
        S1 += __shfl_xor_sync(0xffffffffu, S1, off);
        S2 += __shfl_xor_sync(0xffffffffu, S2, off);
    }
    if (lane == 0) {
        int h = wg;
        float ig = 1.f / (1.f + expf(-g_gates[h]));
        float og = 1.f / (1.f + expf(-g_gates[HH + h]));
        float gg = tanhf(g_gates[2 * HH + h]);
        float E0 = expf(ig);
        float denom = E0 + S1 + 1e-12f;
        float c1 = (gg * E0 + S2) / denom;
        float h1 = og * tanhf(c1);
        out[h] = h1;
        if (out_size >= 2 * HH) out[HH + h] = c1;
    }
}

// ----------------------------------------------------------------
extern "C" void kernel_launch(void* const* d_in, const int* in_sizes, int n_in,
                              void* d_out, int out_size) {
    (void)in_sizes; (void)n_in;
    const float* input_  = (const float*)d_in[0];
    const float* c_input = (const float*)d_in[1];
    const float* h_0     = (const float*)d_in[2];
    /* d_in[3] = c_0, unused by the non-empty-children branch */
    const float* w_ih    = (const float*)d_in[4];
    const float* w_hh    = (const float*)d_in[5];
    const float* bias    = (const float*)d_in[6];
    const float* aw_ih   = (const float*)d_in[7];
    const float* aw_hh   = (const float*)d_in[8];

    cudaFuncSetAttribute(k_main, cudaFuncAttributeMaxDynamicSharedMemorySize, SMEM_TOTAL);

    k_prep<<<256 + 128, 256>>>(aw_hh, input_, h_0, w_ih, w_hh, bias, aw_ih);
    k_main<<<dim3(HH / BN, MT), 256, SMEM_TOTAL>>>(c_input);
    k_final<<<64, 256>>>((float*)d_out, out_size);
}